// round 6
// baseline (speedup 1.0000x reference)
#include <cuda_runtime.h>

#define SZ_OUT (64ull * 1024ull * 64ull)
#define STRIP 1028

typedef unsigned long long u64;

__device__ __forceinline__ u64 pk2(float x) {
    u64 r; asm("mov.b64 %0, {%1, %1};" : "=l"(r) : "f"(x)); return r;
}
__device__ __forceinline__ float2 upk2(u64 p) {
    float2 v; asm("mov.b64 {%0, %1}, %2;" : "=f"(v.x), "=f"(v.y) : "l"(p)); return v;
}
__device__ __forceinline__ u64 ffma2(u64 a, u64 b, u64 c) {
    u64 d; asm("fma.rn.f32x2 %0, %1, %2, %3;" : "=l"(d) : "l"(a), "l"(b), "l"(c)); return d;
}
__device__ __forceinline__ float4 unpack4(u64 a, u64 b) {
    float2 lo = upk2(a), hi = upk2(b);
    return make_float4(lo.x, lo.y, hi.x, hi.y);
}

// ---------------------------------------------------------------------------
// Kernel 1: bias[b,q,k] = sum_d Q[b,q,d] * R_k[q,k,d]  (scratch in attn region)
// Grid (16 k-tiles, 1024 q), 256 thr. Thread tile 4b x 4k, packed over k.
// Warp layout: b-group = tid&15 (16/warp -> 2 phases), k-group = tid>>4 (2/warp
// -> broadcast) => LDS 3 cyc/warp/d, FFMA2 32 cyc/SM/d: FMA-bound.
// ---------------------------------------------------------------------------
__global__ void __launch_bounds__(256) k_bias(const float* __restrict__ Q,
                                              const float* __restrict__ Rk,
                                              float* __restrict__ attn)
{
    const int q  = blockIdx.y;
    const int k0 = blockIdx.x << 6;
    if (k0 > q) return;

    __shared__ float sQd[64 * 68];   // [d][b]
    __shared__ float sRt[64 * 68];   // [d][kk]
    const int tid = threadIdx.x;

    #pragma unroll
    for (int i = 0; i < 16; i++) {
        int f = tid + (i << 8); int b = f >> 6, d = f & 63;
        sQd[d * 68 + b] = Q[((size_t)b << 16) + ((size_t)q << 6) + d];
    }
    #pragma unroll
    for (int i = 0; i < 16; i++) {
        int f = tid + (i << 8); int kk = f >> 6, d = f & 63;
        sRt[d * 68 + kk] = Rk[(((size_t)q << 10) + (size_t)(k0 + kk)) * 64 + d];
    }
    __syncthreads();

    const int b0  = (tid & 15) << 2;
    const int kk0 = (tid >> 4) << 2;
    u64 acc[4][2] = {};
    #pragma unroll 4
    for (int d = 0; d < 64; d++) {
        float4 qv = *(const float4*)&sQd[d * 68 + b0];
        ulonglong2 rp = *(const ulonglong2*)&sRt[d * 68 + kk0];
        u64 qb[4] = {pk2(qv.x), pk2(qv.y), pk2(qv.z), pk2(qv.w)};
        #pragma unroll
        for (int i = 0; i < 4; i++) {
            acc[i][0] = ffma2(qb[i], rp.x, acc[i][0]);
            acc[i][1] = ffma2(qb[i], rp.y, acc[i][1]);
        }
    }
    #pragma unroll
    for (int i = 0; i < 4; i++) {
        size_t base = ((size_t)(b0 + i) << 20) + ((size_t)q << 10) + (size_t)(k0 + kk0);
        *(float4*)&attn[base] = unpack4(acc[i][0], acc[i][1]);
    }
}

// ---------------------------------------------------------------------------
// Kernel 2: per (b, 32-row q strip). 512 threads, ~205 KB smem.
// ---------------------------------------------------------------------------
__global__ void __launch_bounds__(512) k_attn(const float* __restrict__ Q,
                                              const float* __restrict__ K,
                                              const float* __restrict__ V,
                                              float* attn,
                                              float* __restrict__ out)
{
    extern __shared__ float sm[];
    float* strip = sm;                          // [32][1028]
    float* sQd   = strip + 32 * STRIP;          // [d][qi] stride 36
    float* sKV   = sQd + 64 * 36;               // phase1: [d][kk] stride 260; phase4: [kk][d] stride 68 (256 rows)
    __shared__ float sInv[32];

    const int b   = blockIdx.x;
    const int q0  = (gridDim.y - 1 - blockIdx.y) << 5;   // big strips first
    const int tid = threadIdx.x;
    const int ntile = (q0 + 32 + 255) >> 8;

    #pragma unroll
    for (int i = 0; i < 4; i++) {
        int f = tid + (i << 9); int qi = f >> 6, d = f & 63;
        sQd[d * 36 + qi] = Q[((size_t)b << 16) + ((size_t)(q0 + qi) << 6) + d];
    }

    // ---- phase 1: scores.  Tile 4q x 4k, warp: 8 q-groups x 4 k-groups ----
    const int qi0 = (tid & 7) << 2;
    const int kx0 = (tid >> 3) << 2;

    for (int kt = 0; kt < ntile; kt++) {
        const int k0 = kt << 8;
        __syncthreads();
        #pragma unroll
        for (int i = 0; i < 32; i++) {
            int f = tid + (i << 9); int kk = f >> 6, d = f & 63;
            sKV[d * 260 + kk] = K[((size_t)b << 16) + ((size_t)(k0 + kk) << 6) + d];
        }
        __syncthreads();

        u64 acc[4][2] = {};
        #pragma unroll 4
        for (int d = 0; d < 64; d++) {
            float4 qv = *(const float4*)&sQd[d * 36 + qi0];
            ulonglong2 kp = *(const ulonglong2*)&sKV[d * 260 + kx0];
            u64 qb[4] = {pk2(qv.x), pk2(qv.y), pk2(qv.z), pk2(qv.w)};
            #pragma unroll
            for (int i = 0; i < 4; i++) {
                acc[i][0] = ffma2(qb[i], kp.x, acc[i][0]);
                acc[i][1] = ffma2(qb[i], kp.y, acc[i][1]);
            }
        }
        #pragma unroll
        for (int i = 0; i < 4; i++) {
            const int q_row = q0 + qi0 + i;
            const int kg = k0 + kx0;
            float4 av = unpack4(acc[i][0], acc[i][1]);
            float4 bs = *(const float4*)&attn[((size_t)b << 20) + ((size_t)q_row << 10) + kg];
            float s0 = (kg     <= q_row) ? (av.x + bs.x) * 0.125f : 0.f;
            float s1 = (kg + 1 <= q_row) ? (av.y + bs.y) * 0.125f : 0.f;
            float s2 = (kg + 2 <= q_row) ? (av.z + bs.z) * 0.125f : 0.f;
            float s3 = (kg + 3 <= q_row) ? (av.w + bs.w) * 0.125f : 0.f;
            *(float4*)&strip[(qi0 + i) * STRIP + kg] = make_float4(s0, s1, s2, s3);
        }
    }
    __syncthreads();

    // ---- phase 2: softmax per row (16 warps, 2 rows each) ----
    {
        const int lane = tid & 31, w = tid >> 5;
        #pragma unroll
        for (int r = 0; r < 2; r++) {
            int row = (w << 1) + r;
            int qr  = q0 + row;
            float m = -1e30f;
            for (int kk = lane; kk <= qr; kk += 32)
                m = fmaxf(m, strip[row * STRIP + kk]);
            #pragma unroll
            for (int o = 16; o; o >>= 1)
                m = fmaxf(m, __shfl_xor_sync(0xffffffffu, m, o));
            float ssum = 0.f;
            for (int kk = lane; kk <= qr; kk += 32) {
                float e = __expf(strip[row * STRIP + kk] - m);
                strip[row * STRIP + kk] = e;
                ssum += e;
            }
            #pragma unroll
            for (int o = 16; o; o >>= 1)
                ssum += __shfl_xor_sync(0xffffffffu, ssum, o);
            if (lane == 0) sInv[row] = 1.0f / ssum;
        }
    }
    __syncthreads();

    // ---- phase 3: write normalized attn ----
    #pragma unroll
    for (int i = 0; i < 16; i++) {
        int f = tid + (i << 9);
        int row = f >> 8;
        int kc  = (f & 255) << 2;
        int qr  = q0 + row;
        float inv = sInv[row];
        float4 e = *(const float4*)&strip[row * STRIP + kc];
        float4 o;
        o.x = (kc     <= qr) ? e.x * inv : 0.f;
        o.y = (kc + 1 <= qr) ? e.y * inv : 0.f;
        o.z = (kc + 2 <= qr) ? e.z * inv : 0.f;
        o.w = (kc + 3 <= qr) ? e.w * inv : 0.f;
        *(float4*)&attn[((size_t)b << 20) + ((size_t)qr << 10) + kc] = o;
    }

    // ---- phase 4: out = attn @ v. 4-way split-K, tile 4q x 4d, packed over d.
    // Warp: 8 r-groups x 4 d-groups (both operands 1 crossbar phase). ----
    const int g    = tid >> 7;
    const int tid2 = tid & 127;
    const int r0   = (tid2 & 7) << 2;
    const int d0   = (tid2 >> 3) << 2;
    u64 oacc[4][2] = {};

    for (int kt = 0; kt < ntile; kt++) {
        const int k0 = kt << 8;
        __syncthreads();
        #pragma unroll
        for (int i = 0; i < 32; i++) {
            int f = tid + (i << 9); int kk = f >> 6, d = f & 63;
            sKV[kk * 68 + d] = V[((size_t)b << 16) + ((size_t)(k0 + kk) << 6) + d];
        }
        __syncthreads();
        const int kl0 = g << 6;                 // local kk base for this group
        #pragma unroll 2
        for (int kk4 = 0; kk4 < 64; kk4 += 4) {
            float p[4][4];
            #pragma unroll
            for (int i = 0; i < 4; i++)
                *(float4*)p[i] = *(const float4*)&strip[(r0 + i) * STRIP + k0 + kl0 + kk4];
            #pragma unroll
            for (int j = 0; j < 4; j++) {
                ulonglong2 vp = *(const ulonglong2*)&sKV[(kl0 + kk4 + j) * 68 + d0];
                #pragma unroll
                for (int i = 0; i < 4; i++) {
                    u64 pb = pk2(p[i][j]);
                    oacc[i][0] = ffma2(pb, vp.x, oacc[i][0]);
                    oacc[i][1] = ffma2(pb, vp.y, oacc[i][1]);
                }
            }
        }
    }
    __syncthreads();
    // groups 1..3 deposit partials into strip region (reused as reduce buffer)
    float* red = strip;
    if (g > 0) {
        #pragma unroll
        for (int i = 0; i < 4; i++)
            *(float4*)&red[((g - 1) << 11) + ((r0 + i) << 6) + d0] =
                unpack4(oacc[i][0], oacc[i][1]);
    }
    __syncthreads();
    if (g == 0) {
        #pragma unroll
        for (int i = 0; i < 4; i++) {
            float4 s = unpack4(oacc[i][0], oacc[i][1]);
            #pragma unroll
            for (int gg = 0; gg < 3; gg++) {
                float4 p = *(const float4*)&red[(gg << 11) + ((r0 + i) << 6) + d0];
                s.x += p.x; s.y += p.y; s.z += p.z; s.w += p.w;
            }
            float inv = sInv[r0 + i];
            s.x *= inv; s.y *= inv; s.z *= inv; s.w *= inv;
            *(float4*)&out[((size_t)b << 16) + ((size_t)(q0 + r0 + i) << 6) + d0] = s;
        }
    }
}

// ---------------------------------------------------------------------------
// Kernel 3: out[b,q,d] += sum_k attn[b,q,k] * R_v[q,k,d].  Grid 1024 (desc q).
// Tile 4b x 4d packed over d. Warp: 16 b-groups (2 phases) x 2 d-groups (bcast).
// ---------------------------------------------------------------------------
__global__ void __launch_bounds__(256) k_rv(const float* __restrict__ attn,
                                            const float* __restrict__ Rv,
                                            float* __restrict__ out)
{
    const int q   = 1023 - blockIdx.x;          // big work first
    const int tid = threadIdx.x;
    const int ntile = (q >> 6) + 1;

    __shared__ float sAt[64 * 68];   // [kk][b]
    __shared__ float sRt[64 * 68];   // [kk][d]

    const int b0 = (tid & 15) << 2;
    const int d0 = (tid >> 4) << 2;
    u64 acc[4][2] = {};

    for (int kt = 0; kt < ntile; kt++) {
        const int k0 = kt << 6;
        __syncthreads();
        #pragma unroll
        for (int i = 0; i < 16; i++) {
            int f = tid + (i << 8); int bb = f >> 6, kk = f & 63;
            sAt[kk * 68 + bb] = attn[((size_t)bb << 20) + ((size_t)q << 10) + (size_t)(k0 + kk)];
        }
        #pragma unroll
        for (int i = 0; i < 16; i++) {
            int f = tid + (i << 8); int kk = f >> 6, d = f & 63;
            sRt[kk * 68 + d] = Rv[(((size_t)q << 10) + (size_t)(k0 + kk)) * 64 + d];
        }
        __syncthreads();
        #pragma unroll 4
        for (int kk = 0; kk < 64; kk++) {
            float4 a = *(const float4*)&sAt[kk * 68 + b0];
            ulonglong2 rp = *(const ulonglong2*)&sRt[kk * 68 + d0];
            u64 ab[4] = {pk2(a.x), pk2(a.y), pk2(a.z), pk2(a.w)};
            #pragma unroll
            for (int i = 0; i < 4; i++) {
                acc[i][0] = ffma2(ab[i], rp.x, acc[i][0]);
                acc[i][1] = ffma2(ab[i], rp.y, acc[i][1]);
            }
        }
    }
    #pragma unroll
    for (int i = 0; i < 4; i++) {
        size_t ob = ((size_t)(b0 + i) << 16) + ((size_t)q << 6) + d0;
        float4 s = unpack4(acc[i][0], acc[i][1]);
        float4 o = *(float4*)&out[ob];
        o.x += s.x; o.y += s.y; o.z += s.z; o.w += s.w;
        *(float4*)&out[ob] = o;
    }
}

// ---------------------------------------------------------------------------
extern "C" void kernel_launch(void* const* d_in, const int* in_sizes, int n_in,
                              void* d_out, int out_size)
{
    const float* Q  = (const float*)d_in[0];
    const float* K  = (const float*)d_in[1];
    const float* V  = (const float*)d_in[2];
    const float* Rk = (const float*)d_in[3];
    const float* Rv = (const float*)d_in[4];
    float* out  = (float*)d_out;
    float* attn = out + SZ_OUT;

    const int smem2 = (32 * STRIP + 64 * 36 + 256 * 68) * (int)sizeof(float);
    cudaFuncSetAttribute(k_attn, cudaFuncAttributeMaxDynamicSharedMemorySize, smem2);

    k_bias<<<dim3(16, 1024), 256>>>(Q, Rk, attn);
    k_attn<<<dim3(64, 32), 512, smem2>>>(Q, K, V, attn, out);
    k_rv<<<1024, 256>>>(attn, Rv, out);
}

// round 7
// speedup vs baseline: 1.1282x; 1.1282x over previous
#include <cuda_runtime.h>

#define SZ_OUT (64ull * 1024ull * 64ull)
#define STRIP 1028

// ---------------------------------------------------------------------------
// Kernel 1: bias[b,q,k] = sum_d Q[b,q,d] * R_k[q,k,d]  (scratch in attn region)
// Grid (16 k-tiles, 1024 q), 256 thr, thread tile 4b x 4k.
// Warp covers 8 b-groups x 4 k-groups -> 1 wf per operand per d.
// ---------------------------------------------------------------------------
__global__ void __launch_bounds__(256) k_bias(const float* __restrict__ Q,
                                              const float* __restrict__ Rk,
                                              float* __restrict__ attn)
{
    const int q  = blockIdx.y;
    const int k0 = blockIdx.x << 6;
    if (k0 > q) return;

    __shared__ float sQd[64 * 68];   // [d][b]
    __shared__ float sRt[64 * 68];   // [d][kk]
    const int tid = threadIdx.x;

    #pragma unroll
    for (int i = 0; i < 16; i++) {
        int f = tid + (i << 8); int b = f >> 6, d = f & 63;
        sQd[d * 68 + b] = Q[((size_t)b << 16) + ((size_t)q << 6) + d];
    }
    #pragma unroll
    for (int i = 0; i < 16; i++) {
        int f = tid + (i << 8); int kk = f >> 6, d = f & 63;
        sRt[d * 68 + kk] = Rk[(((size_t)q << 10) + (size_t)(k0 + kk)) * 64 + d];
    }
    __syncthreads();

    // 2D warp tile: in-warp 8 b-groups (bits 0-2) x 4 k-groups (bits 3-4)
    const int b0  = ((tid & 7) | ((tid >> 7) << 3)) << 2;   // 16 b-groups
    const int kk0 = ((tid >> 3) & 15) << 2;                  // 16 k-groups
    float acc[4][4] = {};
    #pragma unroll 8
    for (int d = 0; d < 64; d++) {
        float4 qv = *(const float4*)&sQd[d * 68 + b0];
        float4 rv = *(const float4*)&sRt[d * 68 + kk0];
        float qa[4] = {qv.x, qv.y, qv.z, qv.w};
        float ra[4] = {rv.x, rv.y, rv.z, rv.w};
        #pragma unroll
        for (int i = 0; i < 4; i++)
            #pragma unroll
            for (int j = 0; j < 4; j++)
                acc[i][j] = fmaf(qa[i], ra[j], acc[i][j]);
    }
    #pragma unroll
    for (int i = 0; i < 4; i++) {
        size_t base = ((size_t)(b0 + i) << 20) + ((size_t)q << 10) + (size_t)(k0 + kk0);
        *(float4*)&attn[base] = make_float4(acc[i][0], acc[i][1], acc[i][2], acc[i][3]);
    }
}

// ---------------------------------------------------------------------------
// Kernel 2: per (b, 32-row q strip). 512 threads, ~205 KB smem.
// ---------------------------------------------------------------------------
__global__ void __launch_bounds__(512) k_attn(const float* __restrict__ Q,
                                              const float* __restrict__ K,
                                              const float* __restrict__ V,
                                              float* attn,
                                              float* __restrict__ out)
{
    extern __shared__ float sm[];
    float* strip = sm;                          // [32][1028]
    float* sQd   = strip + 32 * STRIP;          // [d][qi] stride 36 (also reduce buf)
    float* sKV   = sQd + 64 * 36;               // phase1: [d][kk] s260; phase4: [kk][d] s68 x256
    __shared__ float sInv[32];

    const int b   = blockIdx.x;
    const int q0  = (gridDim.y - 1 - blockIdx.y) << 5;   // big strips first
    const int tid = threadIdx.x;
    const int ntile = (q0 + 32 + 255) >> 8;

    #pragma unroll
    for (int i = 0; i < 4; i++) {
        int f = tid + (i << 9); int qi = f >> 6, d = f & 63;
        sQd[d * 36 + qi] = Q[((size_t)b << 16) + ((size_t)(q0 + qi) << 6) + d];
    }

    // ---- phase 1: scores. Thread tile 4q x 4k; warp = 8 qg x 4 kg ----
    const int qi0 = (tid & 7) << 2;       // 8 q-groups
    const int kx0 = (tid >> 3) << 2;      // 64 k-groups

    for (int kt = 0; kt < ntile; kt++) {
        const int k0 = kt << 8;
        __syncthreads();
        #pragma unroll
        for (int i = 0; i < 32; i++) {
            int f = tid + (i << 9); int kk = f >> 6, d = f & 63;
            sKV[d * 260 + kk] = K[((size_t)b << 16) + ((size_t)(k0 + kk) << 6) + d];
        }
        __syncthreads();

        float acc[4][4] = {};
        #pragma unroll 8
        for (int d = 0; d < 64; d++) {
            float4 qv = *(const float4*)&sQd[d * 36 + qi0];
            float4 kv = *(const float4*)&sKV[d * 260 + kx0];
            float qa[4] = {qv.x, qv.y, qv.z, qv.w};
            float ka[4] = {kv.x, kv.y, kv.z, kv.w};
            #pragma unroll
            for (int i = 0; i < 4; i++)
                #pragma unroll
                for (int j = 0; j < 4; j++)
                    acc[i][j] = fmaf(qa[i], ka[j], acc[i][j]);
        }
        #pragma unroll
        for (int i = 0; i < 4; i++) {
            const int q_row = q0 + qi0 + i;
            const int kg = k0 + kx0;
            float4 bs = *(const float4*)&attn[((size_t)b << 20) + ((size_t)q_row << 10) + kg];
            float s0 = (kg     <= q_row) ? (acc[i][0] + bs.x) * 0.125f : 0.f;
            float s1 = (kg + 1 <= q_row) ? (acc[i][1] + bs.y) * 0.125f : 0.f;
            float s2 = (kg + 2 <= q_row) ? (acc[i][2] + bs.z) * 0.125f : 0.f;
            float s3 = (kg + 3 <= q_row) ? (acc[i][3] + bs.w) * 0.125f : 0.f;
            *(float4*)&strip[(qi0 + i) * STRIP + kg] = make_float4(s0, s1, s2, s3);
        }
    }
    __syncthreads();

    // ---- phase 2: softmax per row (16 warps, 2 rows each) ----
    {
        const int lane = tid & 31, w = tid >> 5;
        #pragma unroll
        for (int r = 0; r < 2; r++) {
            int row = (w << 1) + r;
            int qr  = q0 + row;
            float m = -1e30f;
            for (int kk = lane; kk <= qr; kk += 32)
                m = fmaxf(m, strip[row * STRIP + kk]);
            #pragma unroll
            for (int o = 16; o; o >>= 1)
                m = fmaxf(m, __shfl_xor_sync(0xffffffffu, m, o));
            float ssum = 0.f;
            for (int kk = lane; kk <= qr; kk += 32) {
                float e = __expf(strip[row * STRIP + kk] - m);
                strip[row * STRIP + kk] = e;
                ssum += e;
            }
            #pragma unroll
            for (int o = 16; o; o >>= 1)
                ssum += __shfl_xor_sync(0xffffffffu, ssum, o);
            if (lane == 0) sInv[row] = 1.0f / ssum;
        }
    }
    __syncthreads();

    // ---- phase 3: write normalized attn ----
    #pragma unroll
    for (int i = 0; i < 16; i++) {
        int f = tid + (i << 9);
        int row = f >> 8;
        int kc  = (f & 255) << 2;
        int qr  = q0 + row;
        float inv = sInv[row];
        float4 e = *(const float4*)&strip[row * STRIP + kc];
        float4 o;
        o.x = (kc     <= qr) ? e.x * inv : 0.f;
        o.y = (kc + 1 <= qr) ? e.y * inv : 0.f;
        o.z = (kc + 2 <= qr) ? e.z * inv : 0.f;
        o.w = (kc + 3 <= qr) ? e.w * inv : 0.f;
        *(float4*)&attn[((size_t)b << 20) + ((size_t)qr << 10) + kc] = o;
    }

    // ---- phase 4: out = attn @ v. 2-way split-K, thread tile 2q x 4d.
    // Warp = 8 r-groups x 4 d-groups; strip read as float4 over kk. ----
    const int g    = tid >> 8;
    const int tid2 = tid & 255;
    const int r0   = ((tid2 & 7) | ((tid2 >> 7) << 3)) << 1;  // 16 r-groups x 2q
    const int d0   = ((tid2 >> 3) & 15) << 2;                  // 16 d-groups x 4d
    float oacc[2][4] = {};

    for (int kt = 0; kt < ntile; kt++) {
        const int k0 = kt << 8;
        __syncthreads();
        #pragma unroll
        for (int i = 0; i < 32; i++) {
            int f = tid + (i << 9); int kk = f >> 6, d = f & 63;
            sKV[kk * 68 + d] = V[((size_t)b << 16) + ((size_t)(k0 + kk) << 6) + d];
        }
        __syncthreads();
        const int kl0 = g << 7;
        #pragma unroll 4
        for (int kk4 = 0; kk4 < 128; kk4 += 4) {
            float p[2][4];
            #pragma unroll
            for (int i = 0; i < 2; i++)
                *(float4*)p[i] = *(const float4*)&strip[(r0 + i) * STRIP + k0 + kl0 + kk4];
            #pragma unroll
            for (int j = 0; j < 4; j++) {
                float4 v = *(const float4*)&sKV[(kl0 + kk4 + j) * 68 + d0];
                #pragma unroll
                for (int i = 0; i < 2; i++) {
                    oacc[i][0] = fmaf(p[i][j], v.x, oacc[i][0]);
                    oacc[i][1] = fmaf(p[i][j], v.y, oacc[i][1]);
                    oacc[i][2] = fmaf(p[i][j], v.z, oacc[i][2]);
                    oacc[i][3] = fmaf(p[i][j], v.w, oacc[i][3]);
                }
            }
        }
    }
    __syncthreads();
    // group 1 deposits partials into sQd (2048 floats), group 0 reduces + writes
    if (g == 1) {
        #pragma unroll
        for (int i = 0; i < 2; i++)
            *(float4*)&sQd[(r0 + i) * 64 + d0] =
                make_float4(oacc[i][0], oacc[i][1], oacc[i][2], oacc[i][3]);
    }
    __syncthreads();
    if (g == 0) {
        #pragma unroll
        for (int i = 0; i < 2; i++) {
            float4 p = *(const float4*)&sQd[(r0 + i) * 64 + d0];
            float inv = sInv[r0 + i];
            float4 o;
            o.x = (oacc[i][0] + p.x) * inv;
            o.y = (oacc[i][1] + p.y) * inv;
            o.z = (oacc[i][2] + p.z) * inv;
            o.w = (oacc[i][3] + p.w) * inv;
            *(float4*)&out[((size_t)b << 16) + ((size_t)(q0 + r0 + i) << 6) + d0] = o;
        }
    }
}

// ---------------------------------------------------------------------------
// Kernel 3: out[b,q,d] += sum_k attn[b,q,k] * R_v[q,k,d].  Grid 1024 (desc q).
// Thread tile 4b x 4d; warp = 8 b-groups x 4 d-groups.
// ---------------------------------------------------------------------------
__global__ void __launch_bounds__(256) k_rv(const float* __restrict__ attn,
                                            const float* __restrict__ Rv,
                                            float* __restrict__ out)
{
    const int q   = 1023 - blockIdx.x;
    const int tid = threadIdx.x;
    const int ntile = (q >> 6) + 1;

    __shared__ float sAt[64 * 68];   // [kk][b]
    __shared__ float sRt[64 * 68];   // [kk][d]

    const int b0 = ((tid & 7) | ((tid >> 7) << 3)) << 2;
    const int d0 = ((tid >> 3) & 15) << 2;
    float acc[4][4] = {};

    for (int kt = 0; kt < ntile; kt++) {
        const int k0 = kt << 6;
        __syncthreads();
        #pragma unroll
        for (int i = 0; i < 16; i++) {
            int f = tid + (i << 8); int bb = f >> 6, kk = f & 63;
            sAt[kk * 68 + bb] = attn[((size_t)bb << 20) + ((size_t)q << 10) + (size_t)(k0 + kk)];
        }
        #pragma unroll
        for (int i = 0; i < 16; i++) {
            int f = tid + (i << 8); int kk = f >> 6, d = f & 63;
            sRt[kk * 68 + d] = Rv[(((size_t)q << 10) + (size_t)(k0 + kk)) * 64 + d];
        }
        __syncthreads();
        #pragma unroll 8
        for (int kk = 0; kk < 64; kk++) {
            float4 a = *(const float4*)&sAt[kk * 68 + b0];
            float4 r = *(const float4*)&sRt[kk * 68 + d0];
            float aa[4] = {a.x, a.y, a.z, a.w};
            float rr[4] = {r.x, r.y, r.z, r.w};
            #pragma unroll
            for (int i = 0; i < 4; i++)
                #pragma unroll
                for (int j = 0; j < 4; j++)
                    acc[i][j] = fmaf(aa[i], rr[j], acc[i][j]);
        }
    }
    #pragma unroll
    for (int i = 0; i < 4; i++) {
        size_t ob = ((size_t)(b0 + i) << 16) + ((size_t)q << 6) + d0;
        float4 o = *(float4*)&out[ob];
        o.x += acc[i][0]; o.y += acc[i][1]; o.z += acc[i][2]; o.w += acc[i][3];
        *(float4*)&out[ob] = o;
    }
}

// ---------------------------------------------------------------------------
extern "C" void kernel_launch(void* const* d_in, const int* in_sizes, int n_in,
                              void* d_out, int out_size)
{
    const float* Q  = (const float*)d_in[0];
    const float* K  = (const float*)d_in[1];
    const float* V  = (const float*)d_in[2];
    const float* Rk = (const float*)d_in[3];
    const float* Rv = (const float*)d_in[4];
    float* out  = (float*)d_out;
    float* attn = out + SZ_OUT;

    const int smem2 = (32 * STRIP + 64 * 36 + 256 * 68) * (int)sizeof(float);
    cudaFuncSetAttribute(k_attn, cudaFuncAttributeMaxDynamicSharedMemorySize, smem2);

    k_bias<<<dim3(16, 1024), 256>>>(Q, Rk, attn);
    k_attn<<<dim3(64, 32), 512, smem2>>>(Q, K, V, attn, out);
    k_rv<<<1024, 256>>>(attn, Rv, out);
}

// round 8
// speedup vs baseline: 1.2610x; 1.1177x over previous
#include <cuda_runtime.h>

#define SZ_OUT (64ull * 1024ull * 64ull)
#define STRIP 1028

// ---------------------------------------------------------------------------
// Kernel 1: bias[b,q,k] = sum_d Q[b,q,d] * R_k[q,k,d]  (scratch in attn region)
// Grid (16 k-tiles, 1024 q), 256 thr, thread tile 4b x 4k.
// Warp shape: 16 k-groups x 2 b-groups  -> coalesced STG (256B/row),
// q-operand ~broadcast (2 distinct), R-operand 2 wf.
// ---------------------------------------------------------------------------
__global__ void __launch_bounds__(256) k_bias(const float* __restrict__ Q,
                                              const float* __restrict__ Rk,
                                              float* __restrict__ attn)
{
    const int q  = blockIdx.y;
    const int k0 = blockIdx.x << 6;
    if (k0 > q) return;

    __shared__ float sQd[64 * 68];   // [d][b]
    __shared__ float sRt[64 * 68];   // [d][kk]
    const int tid = threadIdx.x;

    #pragma unroll
    for (int i = 0; i < 16; i++) {
        int f = tid + (i << 8); int b = f >> 6, d = f & 63;
        sQd[d * 68 + b] = Q[((size_t)b << 16) + ((size_t)q << 6) + d];
    }
    #pragma unroll
    for (int i = 0; i < 16; i++) {
        int f = tid + (i << 8); int kk = f >> 6, d = f & 63;
        sRt[d * 68 + kk] = Rk[(((size_t)q << 10) + (size_t)(k0 + kk)) * 64 + d];
    }
    __syncthreads();

    const int b0  = (tid >> 4) << 2;   // 16 b-groups (2 per warp)
    const int kk0 = (tid & 15) << 2;   // 16 k-groups (16 per warp)
    float acc[4][4] = {};
    #pragma unroll 8
    for (int d = 0; d < 64; d++) {
        float4 qv = *(const float4*)&sQd[d * 68 + b0];
        float4 rv = *(const float4*)&sRt[d * 68 + kk0];
        float qa[4] = {qv.x, qv.y, qv.z, qv.w};
        float ra[4] = {rv.x, rv.y, rv.z, rv.w};
        #pragma unroll
        for (int i = 0; i < 4; i++)
            #pragma unroll
            for (int j = 0; j < 4; j++)
                acc[i][j] = fmaf(qa[i], ra[j], acc[i][j]);
    }
    #pragma unroll
    for (int i = 0; i < 4; i++) {
        size_t base = ((size_t)(b0 + i) << 20) + ((size_t)q << 10) + (size_t)(k0 + kk0);
        *(float4*)&attn[base] = make_float4(acc[i][0], acc[i][1], acc[i][2], acc[i][3]);
    }
}

// ---------------------------------------------------------------------------
// Kernel 2: per (b, 32-row q strip). 512 threads, ~205 KB smem.
// ---------------------------------------------------------------------------
__global__ void __launch_bounds__(512) k_attn(const float* __restrict__ Q,
                                              const float* __restrict__ K,
                                              const float* __restrict__ V,
                                              float* attn,
                                              float* __restrict__ out)
{
    extern __shared__ float sm[];
    float* strip = sm;                          // [32][1028]
    float* sQd   = strip + 32 * STRIP;          // [d][qi] stride 36 (also reduce buf)
    float* sKV   = sQd + 64 * 36;               // phase1: [d][kk] s260; phase4: [kk][d] s68 x256
    __shared__ float sInv[32];

    const int b   = blockIdx.x;
    const int q0  = (gridDim.y - 1 - blockIdx.y) << 5;   // big strips first
    const int tid = threadIdx.x;
    const int ntile = (q0 + 32 + 255) >> 8;

    #pragma unroll
    for (int i = 0; i < 4; i++) {
        int f = tid + (i << 9); int qi = f >> 6, d = f & 63;
        sQd[d * 36 + qi] = Q[((size_t)b << 16) + ((size_t)(q0 + qi) << 6) + d];
    }

    // ---- phase 1: scores. Thread tile 4q x 4k; warp: qi uniform, 32 k-groups
    //      -> bias LDG + strip STS 512B-contiguous, q-operand broadcast ----
    const int qi0 = (tid >> 6) << 2;      // warp-uniform q group
    const int kx0 = (tid & 63) << 2;      // 64 k-groups

    for (int kt = 0; kt < ntile; kt++) {
        const int k0 = kt << 8;
        __syncthreads();
        #pragma unroll
        for (int i = 0; i < 32; i++) {
            int f = tid + (i << 9); int kk = f >> 6, d = f & 63;
            sKV[d * 260 + kk] = K[((size_t)b << 16) + ((size_t)(k0 + kk) << 6) + d];
        }
        __syncthreads();

        float acc[4][4] = {};
        #pragma unroll 8
        for (int d = 0; d < 64; d++) {
            float4 qv = *(const float4*)&sQd[d * 36 + qi0];
            float4 kv = *(const float4*)&sKV[d * 260 + kx0];
            float qa[4] = {qv.x, qv.y, qv.z, qv.w};
            float ka[4] = {kv.x, kv.y, kv.z, kv.w};
            #pragma unroll
            for (int i = 0; i < 4; i++)
                #pragma unroll
                for (int j = 0; j < 4; j++)
                    acc[i][j] = fmaf(qa[i], ka[j], acc[i][j]);
        }
        #pragma unroll
        for (int i = 0; i < 4; i++) {
            const int q_row = q0 + qi0 + i;
            const int kg = k0 + kx0;
            float4 bs = *(const float4*)&attn[((size_t)b << 20) + ((size_t)q_row << 10) + kg];
            float s0 = (kg     <= q_row) ? (acc[i][0] + bs.x) * 0.125f : 0.f;
            float s1 = (kg + 1 <= q_row) ? (acc[i][1] + bs.y) * 0.125f : 0.f;
            float s2 = (kg + 2 <= q_row) ? (acc[i][2] + bs.z) * 0.125f : 0.f;
            float s3 = (kg + 3 <= q_row) ? (acc[i][3] + bs.w) * 0.125f : 0.f;
            *(float4*)&strip[(qi0 + i) * STRIP + kg] = make_float4(s0, s1, s2, s3);
        }
    }
    __syncthreads();

    // ---- phase 2: softmax per row (16 warps, 2 rows each) ----
    {
        const int lane = tid & 31, w = tid >> 5;
        #pragma unroll
        for (int r = 0; r < 2; r++) {
            int row = (w << 1) + r;
            int qr  = q0 + row;
            float m = -1e30f;
            for (int kk = lane; kk <= qr; kk += 32)
                m = fmaxf(m, strip[row * STRIP + kk]);
            #pragma unroll
            for (int o = 16; o; o >>= 1)
                m = fmaxf(m, __shfl_xor_sync(0xffffffffu, m, o));
            float ssum = 0.f;
            for (int kk = lane; kk <= qr; kk += 32) {
                float e = __expf(strip[row * STRIP + kk] - m);
                strip[row * STRIP + kk] = e;
                ssum += e;
            }
            #pragma unroll
            for (int o = 16; o; o >>= 1)
                ssum += __shfl_xor_sync(0xffffffffu, ssum, o);
            if (lane == 0) sInv[row] = 1.0f / ssum;
        }
    }
    __syncthreads();

    // ---- phase 3: write normalized attn (row-contiguous per warp) ----
    #pragma unroll
    for (int i = 0; i < 16; i++) {
        int f = tid + (i << 9);
        int row = f >> 8;
        int kc  = (f & 255) << 2;
        int qr  = q0 + row;
        float inv = sInv[row];
        float4 e = *(const float4*)&strip[row * STRIP + kc];
        float4 o;
        o.x = (kc     <= qr) ? e.x * inv : 0.f;
        o.y = (kc + 1 <= qr) ? e.y * inv : 0.f;
        o.z = (kc + 2 <= qr) ? e.z * inv : 0.f;
        o.w = (kc + 3 <= qr) ? e.w * inv : 0.f;
        *(float4*)&attn[((size_t)b << 20) + ((size_t)qr << 10) + kc] = o;
    }

    // ---- phase 4: out = attn @ v. 2-way split-K, thread tile 2q x 4d.
    // Warp: 2 r-groups x 16 d-groups -> out writes 256B-contiguous;
    // strip read float4 over kk (broadcast), v read 2 wf. ----
    const int g    = tid >> 8;
    const int tid2 = tid & 255;
    const int r0   = (tid2 >> 4) << 1;    // 2 q rows
    const int d0   = (tid2 & 15) << 2;    // 4 d cols
    float oacc[2][4] = {};

    for (int kt = 0; kt < ntile; kt++) {
        const int k0 = kt << 8;
        __syncthreads();
        #pragma unroll
        for (int i = 0; i < 32; i++) {
            int f = tid + (i << 9); int kk = f >> 6, d = f & 63;
            sKV[kk * 68 + d] = V[((size_t)b << 16) + ((size_t)(k0 + kk) << 6) + d];
        }
        __syncthreads();
        const int kl0 = g << 7;
        #pragma unroll 4
        for (int kk4 = 0; kk4 < 128; kk4 += 4) {
            float p[2][4];
            #pragma unroll
            for (int i = 0; i < 2; i++)
                *(float4*)p[i] = *(const float4*)&strip[(r0 + i) * STRIP + k0 + kl0 + kk4];
            #pragma unroll
            for (int j = 0; j < 4; j++) {
                float4 v = *(const float4*)&sKV[(kl0 + kk4 + j) * 68 + d0];
                #pragma unroll
                for (int i = 0; i < 2; i++) {
                    oacc[i][0] = fmaf(p[i][j], v.x, oacc[i][0]);
                    oacc[i][1] = fmaf(p[i][j], v.y, oacc[i][1]);
                    oacc[i][2] = fmaf(p[i][j], v.z, oacc[i][2]);
                    oacc[i][3] = fmaf(p[i][j], v.w, oacc[i][3]);
                }
            }
        }
    }
    __syncthreads();
    // group 1 deposits partials into sQd (2048 floats), group 0 reduces + writes
    if (g == 1) {
        #pragma unroll
        for (int i = 0; i < 2; i++)
            *(float4*)&sQd[(r0 + i) * 64 + d0] =
                make_float4(oacc[i][0], oacc[i][1], oacc[i][2], oacc[i][3]);
    }
    __syncthreads();
    if (g == 0) {
        #pragma unroll
        for (int i = 0; i < 2; i++) {
            float4 p = *(const float4*)&sQd[(r0 + i) * 64 + d0];
            float inv = sInv[r0 + i];
            float4 o;
            o.x = (oacc[i][0] + p.x) * inv;
            o.y = (oacc[i][1] + p.y) * inv;
            o.z = (oacc[i][2] + p.z) * inv;
            o.w = (oacc[i][3] + p.w) * inv;
            *(float4*)&out[((size_t)b << 16) + ((size_t)(q0 + r0 + i) << 6) + d0] = o;
        }
    }
}

// ---------------------------------------------------------------------------
// Kernel 3: out[b,q,d] += sum_k attn[b,q,k] * R_v[q,k,d].  Grid 1024 (desc q).
// Thread tile 4b x 4d; warp: 16 d-groups x 2 b-groups -> contiguous out RMW.
// ---------------------------------------------------------------------------
__global__ void __launch_bounds__(256) k_rv(const float* __restrict__ attn,
                                            const float* __restrict__ Rv,
                                            float* __restrict__ out)
{
    const int q   = 1023 - blockIdx.x;
    const int tid = threadIdx.x;
    const int ntile = (q >> 6) + 1;

    __shared__ float sAt[64 * 68];   // [kk][b]
    __shared__ float sRt[64 * 68];   // [kk][d]

    const int b0 = (tid >> 4) << 2;
    const int d0 = (tid & 15) << 2;
    float acc[4][4] = {};

    for (int kt = 0; kt < ntile; kt++) {
        const int k0 = kt << 6;
        __syncthreads();
        #pragma unroll
        for (int i = 0; i < 16; i++) {
            int f = tid + (i << 8); int bb = f >> 6, kk = f & 63;
            sAt[kk * 68 + bb] = attn[((size_t)bb << 20) + ((size_t)q << 10) + (size_t)(k0 + kk)];
        }
        #pragma unroll
        for (int i = 0; i < 16; i++) {
            int f = tid + (i << 8); int kk = f >> 6, d = f & 63;
            sRt[kk * 68 + d] = Rv[(((size_t)q << 10) + (size_t)(k0 + kk)) * 64 + d];
        }
        __syncthreads();
        #pragma unroll 8
        for (int kk = 0; kk < 64; kk++) {
            float4 a = *(const float4*)&sAt[kk * 68 + b0];
            float4 r = *(const float4*)&sRt[kk * 68 + d0];
            float aa[4] = {a.x, a.y, a.z, a.w};
            float rr[4] = {r.x, r.y, r.z, r.w};
            #pragma unroll
            for (int i = 0; i < 4; i++)
                #pragma unroll
                for (int j = 0; j < 4; j++)
                    acc[i][j] = fmaf(aa[i], rr[j], acc[i][j]);
        }
    }
    #pragma unroll
    for (int i = 0; i < 4; i++) {
        size_t ob = ((size_t)(b0 + i) << 16) + ((size_t)q << 6) + d0;
        float4 o = *(float4*)&out[ob];
        o.x += acc[i][0]; o.y += acc[i][1]; o.z += acc[i][2]; o.w += acc[i][3];
        *(float4*)&out[ob] = o;
    }
}

// ---------------------------------------------------------------------------
extern "C" void kernel_launch(void* const* d_in, const int* in_sizes, int n_in,
                              void* d_out, int out_size)
{
    const float* Q  = (const float*)d_in[0];
    const float* K  = (const float*)d_in[1];
    const float* V  = (const float*)d_in[2];
    const float* Rk = (const float*)d_in[3];
    const float* Rv = (const float*)d_in[4];
    float* out  = (float*)d_out;
    float* attn = out + SZ_OUT;

    const int smem2 = (32 * STRIP + 64 * 36 + 256 * 68) * (int)sizeof(float);
    cudaFuncSetAttribute(k_attn, cudaFuncAttributeMaxDynamicSharedMemorySize, smem2);

    k_bias<<<dim3(16, 1024), 256>>>(Q, Rk, attn);
    k_attn<<<dim3(64, 32), 512, smem2>>>(Q, K, V, attn, out);
    k_rv<<<1024, 256>>>(attn, Rv, out);
}

// round 9
// speedup vs baseline: 1.4828x; 1.1759x over previous
#include <cuda_runtime.h>
#include <cuda_bf16.h>

#define SZ_OUT (64ull * 1024ull * 64ull)
#define STRIP 1028

// ===========================================================================
// bf16 split-GEMM helpers (mma.sync m16n8k16, 3-MMA fp32 emulation)
// SMEM layout for a 64-col bf16 tile: row stride 64 elems (128 B); the 16-byte
// chunk cb (0..7) of row r is stored at chunk (cb ^ (r & 7))  -> ldmatrix
// conflict-free, no padding.
// ===========================================================================
__device__ __forceinline__ unsigned pk_bf2(float a, float b) {
    __nv_bfloat162 t = __floats2bfloat162_rn(a, b);
    return *reinterpret_cast<unsigned*>(&t);
}

// store float4 at (r, c) (c % 4 == 0) split into hi/lo bf16 tiles
__device__ __forceinline__ void split_store(__nv_bfloat16* hi, __nv_bfloat16* lo,
                                            int r, int c, float4 v)
{
    int cb  = c >> 3;
    int off = (r << 6) + ((cb ^ (r & 7)) << 3) + (c & 7);
    float hx = __bfloat162float(__float2bfloat16(v.x));
    float hy = __bfloat162float(__float2bfloat16(v.y));
    float hz = __bfloat162float(__float2bfloat16(v.z));
    float hw = __bfloat162float(__float2bfloat16(v.w));
    *(uint2*)(hi + off) = make_uint2(pk_bf2(hx, hy), pk_bf2(hz, hw));
    *(uint2*)(lo + off) = make_uint2(pk_bf2(v.x - hx, v.y - hy),
                                     pk_bf2(v.z - hz, v.w - hw));
}

__device__ __forceinline__ void ldsm4(unsigned* r, unsigned addr) {
    asm volatile("ldmatrix.sync.aligned.m8n8.x4.shared.b16 {%0,%1,%2,%3}, [%4];"
                 : "=r"(r[0]), "=r"(r[1]), "=r"(r[2]), "=r"(r[3]) : "r"(addr));
}
__device__ __forceinline__ void ldsm4t(unsigned* r, unsigned addr) {
    asm volatile("ldmatrix.sync.aligned.m8n8.x4.trans.shared.b16 {%0,%1,%2,%3}, [%4];"
                 : "=r"(r[0]), "=r"(r[1]), "=r"(r[2]), "=r"(r[3]) : "r"(addr));
}
__device__ __forceinline__ void mma_bf16(float* c, const unsigned* a, const unsigned* b) {
    asm volatile("mma.sync.aligned.m16n8k16.row.col.f32.bf16.bf16.f32 "
                 "{%0,%1,%2,%3}, {%4,%5,%6,%7}, {%8,%9}, {%0,%1,%2,%3};"
                 : "+f"(c[0]), "+f"(c[1]), "+f"(c[2]), "+f"(c[3])
                 : "r"(a[0]), "r"(a[1]), "r"(a[2]), "r"(a[3]), "r"(b[0]), "r"(b[1]));
}

// swizzled byte offset of chunk (r, cb) in a 64-col bf16 tile
__device__ __forceinline__ unsigned sw_off(int r, int cb) {
    return (unsigned)((r << 7) + (((cb ^ (r & 7))) << 4));
}

// ---------------------------------------------------------------------------
// Kernel 1: bias[b,q,k] = sum_d Q[b,q,d] * R_k[q,k,d]   (tensor-core version)
// C[64b x 64k] = A[64b x 64d] @ B[64k x 64d]^T.  8 warps: 4(M) x 2(N),
// warp tile m16 x n32, K = 4 steps of 16, 3-MMA bf16 split.
// ---------------------------------------------------------------------------
__global__ void __launch_bounds__(256) k_bias(const float* __restrict__ Q,
                                              const float* __restrict__ Rk,
                                              float* __restrict__ attn)
{
    const int q  = blockIdx.y;
    const int k0 = blockIdx.x << 6;
    if (k0 > q) return;

    __shared__ __align__(16) __nv_bfloat16 aHi[4096], aLo[4096], bHi[4096], bLo[4096];
    const int tid = threadIdx.x;

    #pragma unroll
    for (int i = 0; i < 4; i++) {
        int f = tid + (i << 8); int r = f >> 4, c = (f & 15) << 2;
        float4 v = *(const float4*)&Q[((size_t)r << 16) + ((size_t)q << 6) + c];
        split_store(aHi, aLo, r, c, v);
    }
    #pragma unroll
    for (int i = 0; i < 4; i++) {
        int f = tid + (i << 8); int r = f >> 4, c = (f & 15) << 2;
        float4 v = *(const float4*)&Rk[(((size_t)q << 10) + (size_t)(k0 + r)) * 64 + c];
        split_store(bHi, bLo, r, c, v);
    }
    __syncthreads();

    const int warp = tid >> 5, lane = tid & 31;
    const int wm = (warp & 3) << 4;
    const int wn = (warp >> 2) << 5;

    const unsigned aH = (unsigned)__cvta_generic_to_shared(aHi);
    const unsigned aL = (unsigned)__cvta_generic_to_shared(aLo);
    const unsigned bH = (unsigned)__cvta_generic_to_shared(bHi);
    const unsigned bL = (unsigned)__cvta_generic_to_shared(bLo);

    const int arow = wm + (lane & 15);
    const int lhi  = lane >> 4;

    float c_[4][4] = {};

    #pragma unroll
    for (int ks = 0; ks < 4; ks++) {
        const int cb = (ks << 1) + lhi;
        unsigned a_hi[4], a_lo[4];
        ldsm4(a_hi, aH + sw_off(arow, cb));
        ldsm4(a_lo, aL + sw_off(arow, cb));
        unsigned b_hi[2][4], b_lo[2][4];
        #pragma unroll
        for (int h = 0; h < 2; h++) {
            int brow = wn + (h << 4) + (lane & 15);
            ldsm4(b_hi[h], bH + sw_off(brow, cb));
            ldsm4(b_lo[h], bL + sw_off(brow, cb));
        }
        #pragma unroll
        for (int j = 0; j < 4; j++) {
            const int h = j >> 1, o = j & 1;
            unsigned bh[2] = {b_hi[h][o], b_hi[h][o + 2]};
            unsigned bl[2] = {b_lo[h][o], b_lo[h][o + 2]};
            mma_bf16(c_[j], a_hi, bh);
            mma_bf16(c_[j], a_hi, bl);
            mma_bf16(c_[j], a_lo, bh);
        }
    }

    const int row0 = wm + (lane >> 2);
    const int coll = (lane & 3) << 1;
    #pragma unroll
    for (int j = 0; j < 4; j++) {
        int col = k0 + wn + (j << 3) + coll;
        *(float2*)&attn[((size_t)row0 << 20) + ((size_t)q << 10) + col] =
            make_float2(c_[j][0], c_[j][1]);
        *(float2*)&attn[((size_t)(row0 + 8) << 20) + ((size_t)q << 10) + col] =
            make_float2(c_[j][2], c_[j][3]);
    }
}

// ---------------------------------------------------------------------------
// Kernel 2: per (b, 32-row q strip). 512 threads, ~205 KB smem. (unchanged R7)
// ---------------------------------------------------------------------------
__global__ void __launch_bounds__(512) k_attn(const float* __restrict__ Q,
                                              const float* __restrict__ K,
                                              const float* __restrict__ V,
                                              float* attn,
                                              float* __restrict__ out)
{
    extern __shared__ float sm[];
    float* strip = sm;
    float* sQd   = strip + 32 * STRIP;
    float* sKV   = sQd + 64 * 36;
    __shared__ float sInv[32];

    const int b   = blockIdx.x;
    const int q0  = (gridDim.y - 1 - blockIdx.y) << 5;
    const int tid = threadIdx.x;
    const int ntile = (q0 + 32 + 255) >> 8;

    #pragma unroll
    for (int i = 0; i < 4; i++) {
        int f = tid + (i << 9); int qi = f >> 6, d = f & 63;
        sQd[d * 36 + qi] = Q[((size_t)b << 16) + ((size_t)(q0 + qi) << 6) + d];
    }

    const int qi0 = (tid >> 6) << 2;
    const int kx0 = (tid & 63) << 2;

    for (int kt = 0; kt < ntile; kt++) {
        const int k0 = kt << 8;
        __syncthreads();
        #pragma unroll
        for (int i = 0; i < 32; i++) {
            int f = tid + (i << 9); int kk = f >> 6, d = f & 63;
            sKV[d * 260 + kk] = K[((size_t)b << 16) + ((size_t)(k0 + kk) << 6) + d];
        }
        __syncthreads();

        float acc[4][4] = {};
        #pragma unroll 8
        for (int d = 0; d < 64; d++) {
            float4 qv = *(const float4*)&sQd[d * 36 + qi0];
            float4 kv = *(const float4*)&sKV[d * 260 + kx0];
            float qa[4] = {qv.x, qv.y, qv.z, qv.w};
            float ka[4] = {kv.x, kv.y, kv.z, kv.w};
            #pragma unroll
            for (int i = 0; i < 4; i++)
                #pragma unroll
                for (int j = 0; j < 4; j++)
                    acc[i][j] = fmaf(qa[i], ka[j], acc[i][j]);
        }
        #pragma unroll
        for (int i = 0; i < 4; i++) {
            const int q_row = q0 + qi0 + i;
            const int kg = k0 + kx0;
            float4 bs = *(const float4*)&attn[((size_t)b << 20) + ((size_t)q_row << 10) + kg];
            float s0 = (kg     <= q_row) ? (acc[i][0] + bs.x) * 0.125f : 0.f;
            float s1 = (kg + 1 <= q_row) ? (acc[i][1] + bs.y) * 0.125f : 0.f;
            float s2 = (kg + 2 <= q_row) ? (acc[i][2] + bs.z) * 0.125f : 0.f;
            float s3 = (kg + 3 <= q_row) ? (acc[i][3] + bs.w) * 0.125f : 0.f;
            *(float4*)&strip[(qi0 + i) * STRIP + kg] = make_float4(s0, s1, s2, s3);
        }
    }
    __syncthreads();

    {
        const int lane = tid & 31, w = tid >> 5;
        #pragma unroll
        for (int r = 0; r < 2; r++) {
            int row = (w << 1) + r;
            int qr  = q0 + row;
            float m = -1e30f;
            for (int kk = lane; kk <= qr; kk += 32)
                m = fmaxf(m, strip[row * STRIP + kk]);
            #pragma unroll
            for (int o = 16; o; o >>= 1)
                m = fmaxf(m, __shfl_xor_sync(0xffffffffu, m, o));
            float ssum = 0.f;
            for (int kk = lane; kk <= qr; kk += 32) {
                float e = __expf(strip[row * STRIP + kk] - m);
                strip[row * STRIP + kk] = e;
                ssum += e;
            }
            #pragma unroll
            for (int o = 16; o; o >>= 1)
                ssum += __shfl_xor_sync(0xffffffffu, ssum, o);
            if (lane == 0) sInv[row] = 1.0f / ssum;
        }
    }
    __syncthreads();

    #pragma unroll
    for (int i = 0; i < 16; i++) {
        int f = tid + (i << 9);
        int row = f >> 8;
        int kc  = (f & 255) << 2;
        int qr  = q0 + row;
        float inv = sInv[row];
        float4 e = *(const float4*)&strip[row * STRIP + kc];
        float4 o;
        o.x = (kc     <= qr) ? e.x * inv : 0.f;
        o.y = (kc + 1 <= qr) ? e.y * inv : 0.f;
        o.z = (kc + 2 <= qr) ? e.z * inv : 0.f;
        o.w = (kc + 3 <= qr) ? e.w * inv : 0.f;
        *(float4*)&attn[((size_t)b << 20) + ((size_t)qr << 10) + kc] = o;
    }

    const int g    = tid >> 8;
    const int tid2 = tid & 255;
    const int r0   = (tid2 >> 4) << 1;
    const int d0   = (tid2 & 15) << 2;
    float oacc[2][4] = {};

    for (int kt = 0; kt < ntile; kt++) {
        const int k0 = kt << 8;
        __syncthreads();
        #pragma unroll
        for (int i = 0; i < 32; i++) {
            int f = tid + (i << 9); int kk = f >> 6, d = f & 63;
            sKV[kk * 68 + d] = V[((size_t)b << 16) + ((size_t)(k0 + kk) << 6) + d];
        }
        __syncthreads();
        const int kl0 = g << 7;
        #pragma unroll 4
        for (int kk4 = 0; kk4 < 128; kk4 += 4) {
            float p[2][4];
            #pragma unroll
            for (int i = 0; i < 2; i++)
                *(float4*)p[i] = *(const float4*)&strip[(r0 + i) * STRIP + k0 + kl0 + kk4];
            #pragma unroll
            for (int j = 0; j < 4; j++) {
                float4 v = *(const float4*)&sKV[(kl0 + kk4 + j) * 68 + d0];
                #pragma unroll
                for (int i = 0; i < 2; i++) {
                    oacc[i][0] = fmaf(p[i][j], v.x, oacc[i][0]);
                    oacc[i][1] = fmaf(p[i][j], v.y, oacc[i][1]);
                    oacc[i][2] = fmaf(p[i][j], v.z, oacc[i][2]);
                    oacc[i][3] = fmaf(p[i][j], v.w, oacc[i][3]);
                }
            }
        }
    }
    __syncthreads();
    if (g == 1) {
        #pragma unroll
        for (int i = 0; i < 2; i++)
            *(float4*)&sQd[(r0 + i) * 64 + d0] =
                make_float4(oacc[i][0], oacc[i][1], oacc[i][2], oacc[i][3]);
    }
    __syncthreads();
    if (g == 0) {
        #pragma unroll
        for (int i = 0; i < 2; i++) {
            float4 p = *(const float4*)&sQd[(r0 + i) * 64 + d0];
            float inv = sInv[r0 + i];
            float4 o;
            o.x = (oacc[i][0] + p.x) * inv;
            o.y = (oacc[i][1] + p.y) * inv;
            o.z = (oacc[i][2] + p.z) * inv;
            o.w = (oacc[i][3] + p.w) * inv;
            *(float4*)&out[((size_t)b << 16) + ((size_t)(q0 + r0 + i) << 6) + d0] = o;
        }
    }
}

// ---------------------------------------------------------------------------
// Kernel 3: out[b,q,d] += sum_k attn[b,q,k] * R_v[q,k,d]  (tensor-core version)
// C[64b x 64d] += A[64b x K] @ B[K x 64d].  A row-major (plain ldmatrix),
// B row-major [k][d] (ldmatrix.trans).  K looped in 64-wide tiles.
// ---------------------------------------------------------------------------
__global__ void __launch_bounds__(256) k_rv(const float* __restrict__ attn,
                                            const float* __restrict__ Rv,
                                            float* __restrict__ out)
{
    const int q   = 1023 - blockIdx.x;
    const int tid = threadIdx.x;
    const int ntile = (q >> 6) + 1;

    __shared__ __align__(16) __nv_bfloat16 aHi[4096], aLo[4096], bHi[4096], bLo[4096];

    const int warp = tid >> 5, lane = tid & 31;
    const int wm = (warp & 3) << 4;
    const int wn = (warp >> 2) << 5;

    const unsigned aH = (unsigned)__cvta_generic_to_shared(aHi);
    const unsigned aL = (unsigned)__cvta_generic_to_shared(aLo);
    const unsigned bH = (unsigned)__cvta_generic_to_shared(bHi);
    const unsigned bL = (unsigned)__cvta_generic_to_shared(bLo);

    const int arow = wm + (lane & 15);
    const int lhi  = lane >> 4;

    float c_[4][4] = {};

    for (int kt = 0; kt < ntile; kt++) {
        const int k0 = kt << 6;
        __syncthreads();
        #pragma unroll
        for (int i = 0; i < 4; i++) {
            int f = tid + (i << 8); int r = f >> 4, c = (f & 15) << 2;
            float4 v = *(const float4*)&attn[((size_t)r << 20) + ((size_t)q << 10) + (size_t)(k0 + c)];
            split_store(aHi, aLo, r, c, v);
        }
        #pragma unroll
        for (int i = 0; i < 4; i++) {
            int f = tid + (i << 8); int r = f >> 4, c = (f & 15) << 2;
            float4 v = *(const float4*)&Rv[(((size_t)q << 10) + (size_t)(k0 + r)) * 64 + c];
            split_store(bHi, bLo, r, c, v);
        }
        __syncthreads();

        #pragma unroll
        for (int ks = 0; ks < 4; ks++) {
            const int cb = (ks << 1) + lhi;
            unsigned a_hi[4], a_lo[4];
            ldsm4(a_hi, aH + sw_off(arow, cb));
            ldsm4(a_lo, aL + sw_off(arow, cb));
            // B: rows = kk (k-dim), col chunks = d (n-dim) -> trans load
            unsigned b_hi[2][4], b_lo[2][4];
            #pragma unroll
            for (int h = 0; h < 2; h++) {
                int brow = (ks << 4) + (lane & 15);
                int bcb  = ((wn + (h << 4)) >> 3) + lhi;
                ldsm4t(b_hi[h], bH + sw_off(brow, bcb));
                ldsm4t(b_lo[h], bL + sw_off(brow, bcb));
            }
            #pragma unroll
            for (int j = 0; j < 4; j++) {
                const int h = j >> 1, o = j & 1;
                unsigned bh[2] = {b_hi[h][o << 1], b_hi[h][(o << 1) + 1]};
                unsigned bl[2] = {b_lo[h][o << 1], b_lo[h][(o << 1) + 1]};
                mma_bf16(c_[j], a_hi, bh);
                mma_bf16(c_[j], a_hi, bl);
                mma_bf16(c_[j], a_lo, bh);
            }
        }
    }

    const int row0 = wm + (lane >> 2);
    const int coll = (lane & 3) << 1;
    #pragma unroll
    for (int j = 0; j < 4; j++) {
        int col = wn + (j << 3) + coll;
        {
            float2* p = (float2*)&out[((size_t)row0 << 16) + ((size_t)q << 6) + col];
            float2 o = *p; o.x += c_[j][0]; o.y += c_[j][1]; *p = o;
        }
        {
            float2* p = (float2*)&out[((size_t)(row0 + 8) << 16) + ((size_t)q << 6) + col];
            float2 o = *p; o.x += c_[j][2]; o.y += c_[j][3]; *p = o;
        }
    }
}

// ---------------------------------------------------------------------------
extern "C" void kernel_launch(void* const* d_in, const int* in_sizes, int n_in,
                              void* d_out, int out_size)
{
    const float* Q  = (const float*)d_in[0];
    const float* K  = (const float*)d_in[1];
    const float* V  = (const float*)d_in[2];
    const float* Rk = (const float*)d_in[3];
    const float* Rv = (const float*)d_in[4];
    float* out  = (float*)d_out;
    float* attn = out + SZ_OUT;

    const int smem2 = (32 * STRIP + 64 * 36 + 256 * 68) * (int)sizeof(float);
    cudaFuncSetAttribute(k_attn, cudaFuncAttributeMaxDynamicSharedMemorySize, smem2);

    k_bias<<<dim3(16, 1024), 256>>>(Q, Rk, attn);
    k_attn<<<dim3(64, 32), 512, smem2>>>(Q, K, V, attn, out);
    k_rv<<<1024, 256>>>(attn, Rv, out);
}

// round 10
// speedup vs baseline: 2.2398x; 1.5105x over previous
#include <cuda_runtime.h>
#include <cuda_bf16.h>

#define SZ_OUT (64ull * 1024ull * 64ull)
#define STRIP 1028

// ===========================================================================
// bf16 split-GEMM helpers (mma.sync m16n8k16, 3-MMA fp32 emulation)
// 64-col bf16 tiles; chunk cb (0..7) of row r stored at chunk (cb ^ (r & 7)).
// ===========================================================================
__device__ __forceinline__ unsigned pk_bf2(float a, float b) {
    __nv_bfloat162 t = __floats2bfloat162_rn(a, b);
    return *reinterpret_cast<unsigned*>(&t);
}

__device__ __forceinline__ void split_store(__nv_bfloat16* hi, __nv_bfloat16* lo,
                                            int r, int c, float4 v)
{
    int cb  = c >> 3;
    int off = (r << 6) + ((cb ^ (r & 7)) << 3) + (c & 7);
    float hx = __bfloat162float(__float2bfloat16(v.x));
    float hy = __bfloat162float(__float2bfloat16(v.y));
    float hz = __bfloat162float(__float2bfloat16(v.z));
    float hw = __bfloat162float(__float2bfloat16(v.w));
    *(uint2*)(hi + off) = make_uint2(pk_bf2(hx, hy), pk_bf2(hz, hw));
    *(uint2*)(lo + off) = make_uint2(pk_bf2(v.x - hx, v.y - hy),
                                     pk_bf2(v.z - hz, v.w - hw));
}

__device__ __forceinline__ void ldsm4(unsigned* r, unsigned addr) {
    asm volatile("ldmatrix.sync.aligned.m8n8.x4.shared.b16 {%0,%1,%2,%3}, [%4];"
                 : "=r"(r[0]), "=r"(r[1]), "=r"(r[2]), "=r"(r[3]) : "r"(addr));
}
__device__ __forceinline__ void ldsm4t(unsigned* r, unsigned addr) {
    asm volatile("ldmatrix.sync.aligned.m8n8.x4.trans.shared.b16 {%0,%1,%2,%3}, [%4];"
                 : "=r"(r[0]), "=r"(r[1]), "=r"(r[2]), "=r"(r[3]) : "r"(addr));
}
__device__ __forceinline__ void mma_bf16(float* c, const unsigned* a, const unsigned* b) {
    asm volatile("mma.sync.aligned.m16n8k16.row.col.f32.bf16.bf16.f32 "
                 "{%0,%1,%2,%3}, {%4,%5,%6,%7}, {%8,%9}, {%0,%1,%2,%3};"
                 : "+f"(c[0]), "+f"(c[1]), "+f"(c[2]), "+f"(c[3])
                 : "r"(a[0]), "r"(a[1]), "r"(a[2]), "r"(a[3]), "r"(b[0]), "r"(b[1]));
}

__device__ __forceinline__ unsigned sw_off(int r, int cb) {
    return (unsigned)((r << 7) + (((cb ^ (r & 7))) << 4));
}

// ---------------------------------------------------------------------------
// Kernel 1: bias[b,q,k] = sum_d Q[b,q,d] * R_k[q,k,d]   (unchanged R8)
// ---------------------------------------------------------------------------
__global__ void __launch_bounds__(256) k_bias(const float* __restrict__ Q,
                                              const float* __restrict__ Rk,
                                              float* __restrict__ attn)
{
    const int q  = blockIdx.y;
    const int k0 = blockIdx.x << 6;
    if (k0 > q) return;

    __shared__ __align__(16) __nv_bfloat16 aHi[4096], aLo[4096], bHi[4096], bLo[4096];
    const int tid = threadIdx.x;

    #pragma unroll
    for (int i = 0; i < 4; i++) {
        int f = tid + (i << 8); int r = f >> 4, c = (f & 15) << 2;
        float4 v = *(const float4*)&Q[((size_t)r << 16) + ((size_t)q << 6) + c];
        split_store(aHi, aLo, r, c, v);
    }
    #pragma unroll
    for (int i = 0; i < 4; i++) {
        int f = tid + (i << 8); int r = f >> 4, c = (f & 15) << 2;
        float4 v = *(const float4*)&Rk[(((size_t)q << 10) + (size_t)(k0 + r)) * 64 + c];
        split_store(bHi, bLo, r, c, v);
    }
    __syncthreads();

    const int warp = tid >> 5, lane = tid & 31;
    const int wm = (warp & 3) << 4;
    const int wn = (warp >> 2) << 5;

    const unsigned aH = (unsigned)__cvta_generic_to_shared(aHi);
    const unsigned aL = (unsigned)__cvta_generic_to_shared(aLo);
    const unsigned bH = (unsigned)__cvta_generic_to_shared(bHi);
    const unsigned bL = (unsigned)__cvta_generic_to_shared(bLo);

    const int arow = wm + (lane & 15);
    const int lhi  = lane >> 4;

    float c_[4][4] = {};

    #pragma unroll
    for (int ks = 0; ks < 4; ks++) {
        const int cb = (ks << 1) + lhi;
        unsigned a_hi[4], a_lo[4];
        ldsm4(a_hi, aH + sw_off(arow, cb));
        ldsm4(a_lo, aL + sw_off(arow, cb));
        unsigned b_hi[2][4], b_lo[2][4];
        #pragma unroll
        for (int h = 0; h < 2; h++) {
            int brow = wn + (h << 4) + (lane & 15);
            ldsm4(b_hi[h], bH + sw_off(brow, cb));
            ldsm4(b_lo[h], bL + sw_off(brow, cb));
        }
        #pragma unroll
        for (int j = 0; j < 4; j++) {
            const int h = j >> 1, o = j & 1;
            unsigned bh[2] = {b_hi[h][o], b_hi[h][o + 2]};
            unsigned bl[2] = {b_lo[h][o], b_lo[h][o + 2]};
            mma_bf16(c_[j], a_hi, bh);
            mma_bf16(c_[j], a_hi, bl);
            mma_bf16(c_[j], a_lo, bh);
        }
    }

    const int row0 = wm + (lane >> 2);
    const int coll = (lane & 3) << 1;
    #pragma unroll
    for (int j = 0; j < 4; j++) {
        int col = k0 + wn + (j << 3) + coll;
        *(float2*)&attn[((size_t)row0 << 20) + ((size_t)q << 10) + col] =
            make_float2(c_[j][0], c_[j][1]);
        *(float2*)&attn[((size_t)(row0 + 8) << 20) + ((size_t)q << 10) + col] =
            make_float2(c_[j][2], c_[j][3]);
    }
}

// ---------------------------------------------------------------------------
// Kernel 2: per (b, 32-row q strip). 512 threads, ~200 KB smem.
// phase1 (tensor): scores = Q@K^T via mma + bias from strip, scale, mask.
// phase2: softmax.  phase3: write attn.  phase4 (tensor): out = P@V.
// ---------------------------------------------------------------------------
__global__ void __launch_bounds__(512) k_attn(const float* __restrict__ Q,
                                              const float* __restrict__ K,
                                              const float* __restrict__ V,
                                              float* attn,
                                              float* __restrict__ out)
{
    extern __shared__ float sm[];
    float* strip = sm;                                      // [32][1028]
    __nv_bfloat16* bufs = (__nv_bfloat16*)(strip + 32 * STRIP);
    // phase1 layout (elems): qHi[2048] qLo[2048] kHi[16384] kLo[16384]
    __nv_bfloat16* qHi = bufs;
    __nv_bfloat16* qLo = bufs + 2048;
    __nv_bfloat16* kHi = bufs + 4096;
    __nv_bfloat16* kLo = bufs + 20480;
    // phase4 layout (aliased): pHi[4096] pLo[4096] vHi[8192] vLo[8192]
    __nv_bfloat16* pHi = bufs;
    __nv_bfloat16* pLo = bufs + 4096;
    __nv_bfloat16* vHi = bufs + 8192;
    __nv_bfloat16* vLo = bufs + 16384;
    float* red = (float*)bufs;                              // reduce buf (24 KB)
    __shared__ float sInv[32];

    const int b   = blockIdx.x;
    const int q0  = (gridDim.y - 1 - blockIdx.y) << 5;
    const int tid = threadIdx.x;
    const int warp = tid >> 5, lane = tid & 31, lhi = lane >> 4;

    // split Q strip (32x64) into qHi/qLo once
    {
        int r = tid >> 4, c = (tid & 15) << 2;
        float4 v = *(const float4*)&Q[((size_t)b << 16) + ((size_t)(q0 + r) << 6) + c];
        split_store(qHi, qLo, r, c, v);
    }

    const unsigned qH = (unsigned)__cvta_generic_to_shared(qHi);
    const unsigned qL = (unsigned)__cvta_generic_to_shared(qLo);
    const unsigned kH = (unsigned)__cvta_generic_to_shared(kHi);
    const unsigned kL = (unsigned)__cvta_generic_to_shared(kLo);

    // ---- phase 1: 256-wide k tiles, 16 warps = 2(m16) x 8(n32) ----
    const int wm1 = (warp & 1) << 4;
    const int wn1 = (warp >> 1) << 5;
    const int ntile1 = (q0 + 32 + 255) >> 8;

    for (int kt = 0; kt < ntile1; kt++) {
        const int k0 = kt << 8;
        __syncthreads();
        // bias preload into strip (coalesced)
        #pragma unroll
        for (int i = 0; i < 4; i++) {
            int f = tid + (i << 9); int row = f >> 6, kc = (f & 63) << 2;
            *(float4*)&strip[row * STRIP + k0 + kc] =
                *(const float4*)&attn[((size_t)b << 20) + ((size_t)(q0 + row) << 10) + k0 + kc];
        }
        // split K tile (256x64)
        #pragma unroll
        for (int i = 0; i < 8; i++) {
            int f = tid + (i << 9); int r = f >> 4, c = (f & 15) << 2;
            float4 v = *(const float4*)&K[((size_t)b << 16) + ((size_t)(k0 + r) << 6) + c];
            split_store(kHi, kLo, r, c, v);
        }
        __syncthreads();

        float c_[4][4] = {};
        const int arow = wm1 + (lane & 15);
        #pragma unroll
        for (int ks = 0; ks < 4; ks++) {
            const int cb = (ks << 1) + lhi;
            unsigned a_hi[4], a_lo[4];
            ldsm4(a_hi, qH + sw_off(arow, cb));
            ldsm4(a_lo, qL + sw_off(arow, cb));
            unsigned b_hi[2][4], b_lo[2][4];
            #pragma unroll
            for (int h = 0; h < 2; h++) {
                int brow = wn1 + (h << 4) + (lane & 15);
                ldsm4(b_hi[h], kH + sw_off(brow, cb));
                ldsm4(b_lo[h], kL + sw_off(brow, cb));
            }
            #pragma unroll
            for (int j = 0; j < 4; j++) {
                const int h = j >> 1, o = j & 1;
                unsigned bh[2] = {b_hi[h][o], b_hi[h][o + 2]};
                unsigned bl[2] = {b_lo[h][o], b_lo[h][o + 2]};
                mma_bf16(c_[j], a_hi, bh);
                mma_bf16(c_[j], a_hi, bl);
                mma_bf16(c_[j], a_lo, bh);
            }
        }
        // epilogue: scores = (mma + bias)*0.125, causal mask -> strip
        const int row0 = wm1 + (lane >> 2);
        const int coll = (lane & 3) << 1;
        #pragma unroll
        for (int j = 0; j < 4; j++) {
            int colk = k0 + wn1 + (j << 3) + coll;
            {
                int qr = q0 + row0;
                float2 bs = *(float2*)&strip[row0 * STRIP + colk];
                float s0 = (colk     <= qr) ? (c_[j][0] + bs.x) * 0.125f : 0.f;
                float s1 = (colk + 1 <= qr) ? (c_[j][1] + bs.y) * 0.125f : 0.f;
                *(float2*)&strip[row0 * STRIP + colk] = make_float2(s0, s1);
            }
            {
                int qr = q0 + row0 + 8;
                float2 bs = *(float2*)&strip[(row0 + 8) * STRIP + colk];
                float s0 = (colk     <= qr) ? (c_[j][2] + bs.x) * 0.125f : 0.f;
                float s1 = (colk + 1 <= qr) ? (c_[j][3] + bs.y) * 0.125f : 0.f;
                *(float2*)&strip[(row0 + 8) * STRIP + colk] = make_float2(s0, s1);
            }
        }
    }
    __syncthreads();

    // ---- phase 2: softmax per row (16 warps, 2 rows each) ----
    {
        const int w = warp;
        #pragma unroll
        for (int r = 0; r < 2; r++) {
            int row = (w << 1) + r;
            int qr  = q0 + row;
            float m = -1e30f;
            for (int kk = lane; kk <= qr; kk += 32)
                m = fmaxf(m, strip[row * STRIP + kk]);
            #pragma unroll
            for (int o = 16; o; o >>= 1)
                m = fmaxf(m, __shfl_xor_sync(0xffffffffu, m, o));
            float ssum = 0.f;
            for (int kk = lane; kk <= qr; kk += 32) {
                float e = __expf(strip[row * STRIP + kk] - m);
                strip[row * STRIP + kk] = e;
                ssum += e;
            }
            #pragma unroll
            for (int o = 16; o; o >>= 1)
                ssum += __shfl_xor_sync(0xffffffffu, ssum, o);
            if (lane == 0) sInv[row] = 1.0f / ssum;
        }
    }
    __syncthreads();

    // ---- phase 3: write normalized attn ----
    #pragma unroll
    for (int i = 0; i < 16; i++) {
        int f = tid + (i << 9);
        int row = f >> 8;
        int kc  = (f & 255) << 2;
        int qr  = q0 + row;
        float inv = sInv[row];
        float4 e = *(const float4*)&strip[row * STRIP + kc];
        float4 o;
        o.x = (kc     <= qr) ? e.x * inv : 0.f;
        o.y = (kc + 1 <= qr) ? e.y * inv : 0.f;
        o.z = (kc + 2 <= qr) ? e.z * inv : 0.f;
        o.w = (kc + 3 <= qr) ? e.w * inv : 0.f;
        *(float4*)&attn[((size_t)b << 20) + ((size_t)qr << 10) + kc] = o;
    }

    // ---- phase 4: out = P @ V.  128-wide k tiles, 16 warps = 2m x 2n x 4kg ----
    const int wm4 = (warp & 1) << 4;
    const int wn4 = ((warp >> 1) & 1) << 5;
    const int kg  = warp >> 2;
    const int ntile4 = (q0 + 32 + 127) >> 7;
    const unsigned pH = (unsigned)__cvta_generic_to_shared(pHi);
    const unsigned pL = (unsigned)__cvta_generic_to_shared(pLo);
    const unsigned vH = (unsigned)__cvta_generic_to_shared(vHi);
    const unsigned vL = (unsigned)__cvta_generic_to_shared(vLo);

    float c4[4][4] = {};

    for (int kt = 0; kt < ntile4; kt++) {
        const int k0 = kt << 7;
        __syncthreads();
        // split P tile (32x128) from strip
        #pragma unroll
        for (int i = 0; i < 2; i++) {
            int f = tid + (i << 9); int r = f >> 5, c = (f & 31) << 2;
            float4 v = *(const float4*)&strip[r * STRIP + k0 + c];
            int kh = c >> 6;
            split_store(pHi + (kh << 11), pLo + (kh << 11), r, c & 63, v);
        }
        // split V tile (128x64)
        #pragma unroll
        for (int i = 0; i < 4; i++) {
            int f = tid + (i << 9); int r = f >> 4, c = (f & 15) << 2;
            float4 v = *(const float4*)&V[((size_t)b << 16) + ((size_t)(k0 + r) << 6) + c];
            split_store(vHi, vLo, r, c, v);
        }
        __syncthreads();

        const int arow = wm4 + (lane & 15);
        #pragma unroll
        for (int ks = 0; ks < 2; ks++) {
            const int ko = (kg << 5) + (ks << 4);
            const int kh = ko >> 6;
            const int cbb = (ko & 63) >> 3;
            unsigned a_hi[4], a_lo[4];
            ldsm4(a_hi, pH + (kh << 12) + sw_off(arow, cbb + lhi));
            ldsm4(a_lo, pL + (kh << 12) + sw_off(arow, cbb + lhi));
            unsigned b_hi[2][4], b_lo[2][4];
            const int brow = ko + (lane & 15);
            #pragma unroll
            for (int h = 0; h < 2; h++) {
                int bcb = ((wn4 + (h << 4)) >> 3) + lhi;
                ldsm4t(b_hi[h], vH + sw_off(brow, bcb));
                ldsm4t(b_lo[h], vL + sw_off(brow, bcb));
            }
            #pragma unroll
            for (int j = 0; j < 4; j++) {
                const int h = j >> 1, o = j & 1;
                unsigned bh[2] = {b_hi[h][o << 1], b_hi[h][(o << 1) + 1]};
                unsigned bl[2] = {b_lo[h][o << 1], b_lo[h][(o << 1) + 1]};
                mma_bf16(c4[j], a_hi, bh);
                mma_bf16(c4[j], a_hi, bl);
                mma_bf16(c4[j], a_lo, bh);
            }
        }
    }
    __syncthreads();

    // split-K reduction across kg groups
    const int row0 = wm4 + (lane >> 2);
    const int coll = (lane & 3) << 1;
    if (kg > 0) {
        #pragma unroll
        for (int j = 0; j < 4; j++) {
            int col = wn4 + (j << 3) + coll;
            *(float2*)&red[((kg - 1) << 11) + (row0 << 6) + col] =
                make_float2(c4[j][0], c4[j][1]);
            *(float2*)&red[((kg - 1) << 11) + ((row0 + 8) << 6) + col] =
                make_float2(c4[j][2], c4[j][3]);
        }
    }
    __syncthreads();
    if (kg == 0) {
        const float inv0 = sInv[row0];
        const float inv1 = sInv[row0 + 8];
        #pragma unroll
        for (int j = 0; j < 4; j++) {
            int col = wn4 + (j << 3) + coll;
            float2 s0 = make_float2(c4[j][0], c4[j][1]);
            float2 s1 = make_float2(c4[j][2], c4[j][3]);
            #pragma unroll
            for (int g = 0; g < 3; g++) {
                float2 p0 = *(const float2*)&red[(g << 11) + (row0 << 6) + col];
                float2 p1 = *(const float2*)&red[(g << 11) + ((row0 + 8) << 6) + col];
                s0.x += p0.x; s0.y += p0.y;
                s1.x += p1.x; s1.y += p1.y;
            }
            *(float2*)&out[((size_t)b << 16) + ((size_t)(q0 + row0) << 6) + col] =
                make_float2(s0.x * inv0, s0.y * inv0);
            *(float2*)&out[((size_t)b << 16) + ((size_t)(q0 + row0 + 8) << 6) + col] =
                make_float2(s1.x * inv1, s1.y * inv1);
        }
    }
}

// ---------------------------------------------------------------------------
// Kernel 3: out[b,q,d] += sum_k attn[b,q,k] * R_v[q,k,d]   (unchanged R8)
// ---------------------------------------------------------------------------
__global__ void __launch_bounds__(256) k_rv(const float* __restrict__ attn,
                                            const float* __restrict__ Rv,
                                            float* __restrict__ out)
{
    const int q   = 1023 - blockIdx.x;
    const int tid = threadIdx.x;
    const int ntile = (q >> 6) + 1;

    __shared__ __align__(16) __nv_bfloat16 aHi[4096], aLo[4096], bHi[4096], bLo[4096];

    const int warp = tid >> 5, lane = tid & 31;
    const int wm = (warp & 3) << 4;
    const int wn = (warp >> 2) << 5;

    const unsigned aH = (unsigned)__cvta_generic_to_shared(aHi);
    const unsigned aL = (unsigned)__cvta_generic_to_shared(aLo);
    const unsigned bH = (unsigned)__cvta_generic_to_shared(bHi);
    const unsigned bL = (unsigned)__cvta_generic_to_shared(bLo);

    const int arow = wm + (lane & 15);
    const int lhi  = lane >> 4;

    float c_[4][4] = {};

    for (int kt = 0; kt < ntile; kt++) {
        const int k0 = kt << 6;
        __syncthreads();
        #pragma unroll
        for (int i = 0; i < 4; i++) {
            int f = tid + (i << 8); int r = f >> 4, c = (f & 15) << 2;
            float4 v = *(const float4*)&attn[((size_t)r << 20) + ((size_t)q << 10) + (size_t)(k0 + c)];
            split_store(aHi, aLo, r, c, v);
        }
        #pragma unroll
        for (int i = 0; i < 4; i++) {
            int f = tid + (i << 8); int r = f >> 4, c = (f & 15) << 2;
            float4 v = *(const float4*)&Rv[(((size_t)q << 10) + (size_t)(k0 + r)) * 64 + c];
            split_store(bHi, bLo, r, c, v);
        }
        __syncthreads();

        #pragma unroll
        for (int ks = 0; ks < 4; ks++) {
            const int cb = (ks << 1) + lhi;
            unsigned a_hi[4], a_lo[4];
            ldsm4(a_hi, aH + sw_off(arow, cb));
            ldsm4(a_lo, aL + sw_off(arow, cb));
            unsigned b_hi[2][4], b_lo[2][4];
            #pragma unroll
            for (int h = 0; h < 2; h++) {
                int brow = (ks << 4) + (lane & 15);
                int bcb  = ((wn + (h << 4)) >> 3) + lhi;
                ldsm4t(b_hi[h], bH + sw_off(brow, bcb));
                ldsm4t(b_lo[h], bL + sw_off(brow, bcb));
            }
            #pragma unroll
            for (int j = 0; j < 4; j++) {
                const int h = j >> 1, o = j & 1;
                unsigned bh[2] = {b_hi[h][o << 1], b_hi[h][(o << 1) + 1]};
                unsigned bl[2] = {b_lo[h][o << 1], b_lo[h][(o << 1) + 1]};
                mma_bf16(c_[j], a_hi, bh);
                mma_bf16(c_[j], a_hi, bl);
                mma_bf16(c_[j], a_lo, bh);
            }
        }
    }

    const int row0 = wm + (lane >> 2);
    const int coll = (lane & 3) << 1;
    #pragma unroll
    for (int j = 0; j < 4; j++) {
        int col = wn + (j << 3) + coll;
        {
            float2* p = (float2*)&out[((size_t)row0 << 16) + ((size_t)q << 6) + col];
            float2 o = *p; o.x += c_[j][0]; o.y += c_[j][1]; *p = o;
        }
        {
            float2* p = (float2*)&out[((size_t)(row0 + 8) << 16) + ((size_t)q << 6) + col];
            float2 o = *p; o.x += c_[j][2]; o.y += c_[j][3]; *p = o;
        }
    }
}

// ---------------------------------------------------------------------------
extern "C" void kernel_launch(void* const* d_in, const int* in_sizes, int n_in,
                              void* d_out, int out_size)
{
    const float* Q  = (const float*)d_in[0];
    const float* K  = (const float*)d_in[1];
    const float* V  = (const float*)d_in[2];
    const float* Rk = (const float*)d_in[3];
    const float* Rv = (const float*)d_in[4];
    float* out  = (float*)d_out;
    float* attn = out + SZ_OUT;

    const int smem2 = 32 * STRIP * (int)sizeof(float) + 36864 * (int)sizeof(__nv_bfloat16);
    cudaFuncSetAttribute(k_attn, cudaFuncAttributeMaxDynamicSharedMemorySize, smem2);

    k_bias<<<dim3(16, 1024), 256>>>(Q, Rk, attn);
    k_attn<<<dim3(64, 32), 512, smem2>>>(Q, K, V, attn, out);
    k_rv<<<1024, 256>>>(attn, Rv, out);
}